// round 9
// baseline (speedup 1.0000x reference)
#include <cuda_runtime.h>
#include <cstdint>

// LSTM_10960756539796: B=256, T=512, D=64, H=256, C=10
// Persistent kernel, 128 CTAs x 512 threads (16 warps).
//   group g = blockIdx/8 -> batch rows [g*16, g*16+16)
//   rank  r = blockIdx%8 -> hidden units [r*32, r*32+32) (128 gate rows)
// Warp w: kh = w>>1 (k-stripe [32kh,32kh+32)), half = w&1 (row half).
// WARP-LOCAL SYNC: warp w waits only on flag[t-1][kh], copies its own h/x
// stripes into private smem buffers, then runs its GEMM with no CTA barrier.
// Only 2 __syncthreads per step (pre-cell, post-cell).

#define TT    512
#define DD    64
#define HH    256
#define NGRP  16
#define NRNK  8
#define BB    16
#define HU    32
#define NL    128
#define NTHR  512
#define NKH   8
#define NWARP 16

typedef unsigned long long u64;

__device__ float g_H[2][256][HH];          // [parity][b][k]
__device__ int   g_flagT[NGRP][TT][NRNK];  // set-once per run, reset at end
__device__ int   g_done[NGRP];

__device__ __forceinline__ u64 fma2(u64 a, u64 b, u64 c) {
    u64 d;
    asm("fma.rn.f32x2 %0, %1, %2, %3;" : "=l"(d) : "l"(a), "l"(b), "l"(c));
    return d;
}
__device__ __forceinline__ float hsum2(u64 v) {
    float lo, hi;
    asm("mov.b64 {%0,%1}, %2;" : "=f"(lo), "=f"(hi) : "l"(v));
    return lo + hi;
}
__device__ __forceinline__ float4 ldcv4(const float* p) {
    float4 v;
    asm volatile("ld.volatile.global.v4.f32 {%0,%1,%2,%3}, [%4];"
                 : "=f"(v.x), "=f"(v.y), "=f"(v.z), "=f"(v.w) : "l"(p));
    return v;
}
__device__ __forceinline__ void stcg(float* p, float v) {
    asm volatile("st.global.cg.f32 [%0], %1;" :: "l"(p), "f"(v));
}
__device__ __forceinline__ int ldacq(const int* p) {
    int v;
    asm volatile("ld.acquire.gpu.global.b32 %0, [%1];" : "=r"(v) : "l"(p));
    return v;
}
__device__ __forceinline__ void strel(int* p, int v) {
    asm volatile("st.release.gpu.global.b32 [%0], %1;" :: "l"(p), "r"(v));
}

// dynamic smem layout (bytes)
#define OFF_HS 0        // h_s[NWARP][BB][32] = 32768 (per-warp private stripes)
#define OFF_XS 32768    // x_s[NWARP][BB][8]  =  8192 (per-warp private stripes)
#define OFF_ZP 40960    // zp[NKH][BB][NL]    = 65536
#define SMEM_BYTES 106496

__global__ __launch_bounds__(NTHR, 1)
void lstm_persistent_kernel(const float* __restrict__ x,
                            const float* __restrict__ W_ih,
                            const float* __restrict__ W_hh,
                            const float* __restrict__ b_ih,
                            const float* __restrict__ b_hh,
                            const float* __restrict__ W_out,
                            const float* __restrict__ b_out,
                            float* __restrict__ out)
{
    extern __shared__ __align__(16) char smem_raw[];
    float (*h_s)[BB][32] = (float (*)[BB][32])(smem_raw + OFF_HS);
    float (*x_s)[BB][8]  = (float (*)[BB][8])(smem_raw + OFF_XS);
    float (*zp)[BB][NL]  = (float (*)[BB][NL])(smem_raw + OFF_ZP);

    const int g    = blockIdx.x >> 3;
    const int r    = blockIdx.x & 7;
    const int tid  = threadIdx.x;
    const int lane = tid & 31;
    const int wid  = tid >> 5;
    const int kh   = wid >> 1;          // k-stripe: k in [32kh, 32kh+32)
    const int np   = tid & 63;          // row pair: rows 2np, 2np+1
    const int row0 = 2 * np;
    const int gate = row0 >> 5;
    const int u0   = row0 & 31;
    const int nglob0 = gate * HH + r * HU + u0;
    const int nglob1 = nglob0 + 1;

    // ---- register-resident weights (packed k-pairs), 2 rows x 32 k ----
    u64 W2[32];
    {
        const u64* wp0 = (const u64*)(W_hh + (size_t)nglob0 * HH + kh * 32);
        const u64* wp1 = (const u64*)(W_hh + (size_t)nglob1 * HH + kh * 32);
        #pragma unroll
        for (int i = 0; i < 16; i++) W2[i]      = wp0[i];
        #pragma unroll
        for (int i = 0; i < 16; i++) W2[16 + i] = wp1[i];
    }
    u64 Wi2[8];
    {
        const u64* wp0 = (const u64*)(W_ih + (size_t)nglob0 * DD + kh * 8);
        const u64* wp1 = (const u64*)(W_ih + (size_t)nglob1 * DD + kh * 8);
        #pragma unroll
        for (int i = 0; i < 4; i++) Wi2[i]     = wp0[i];
        #pragma unroll
        for (int i = 0; i < 4; i++) Wi2[4 + i] = wp1[i];
    }
    const float bias0 = b_ih[nglob0] + b_hh[nglob0];  // applied by kh==0 only
    const float bias1 = b_ih[nglob1] + b_hh[nglob1];

    // cell owned by this thread: batch row cb = warp id, unit cu = lane
    const int cb = wid;
    const int cu = lane;
    float creg = 0.0f;

    // zero this warp's private h stripe (h0 = 0)
    #pragma unroll
    for (int i = lane; i < BB * 32; i += 32) (&h_s[wid][0][0])[i] = 0.0f;
    __syncthreads();

    const float* xbase = x + (size_t)(g * BB) * TT * DD;

    // per-warp x stripe addressing: lane l covers (b = l>>1, d = 8kh + (l&1)*4)
    const int bx = lane >> 1;
    const int dx = kh * 8 + (lane & 1) * 4;
    float4 xr = *(const float4*)(xbase + ((size_t)bx * TT + 0) * DD + dx);

    // per-warp h stripe copy addressing: lane l covers (b = l>>1, inner = (l&1)*16)
    const int bh    = lane >> 1;
    const int innh  = (lane & 1) * 16;
    float* hdst = &h_s[wid][bh][innh];

    #pragma unroll 1
    for (int t = 0; t < TT; t++) {
        const int q = t & 1;

        // stash prefetched x stripe (warp-private buffer; no sync needed)
        *(float4*)(&x_s[wid][bx][(lane & 1) * 4]) = xr;

        if (t > 0) {
            // warp-local wait: single flag for this warp's k-stripe
            const int* fp = &g_flagT[g][t - 1][kh];
            while (ldacq(fp) == 0) { __nanosleep(20); }
            // copy this warp's h stripe (16 b x 32 k), 16 floats per lane
            const float* src = &g_H[q][g * BB + bh][kh * 32 + innh];
            float4 v0 = ldcv4(src);
            float4 v1 = ldcv4(src + 4);
            float4 v2 = ldcv4(src + 8);
            float4 v3 = ldcv4(src + 12);
            *(float4*)(hdst)      = v0;
            *(float4*)(hdst + 4)  = v1;
            *(float4*)(hdst + 8)  = v2;
            *(float4*)(hdst + 12) = v3;
        }
        // NO CTA barrier: GEMM reads only warp-private h_s[wid]/x_s[wid]

        // ---- GEMM partials: 2 rows x 32 k per thread ----
        #pragma unroll 1
        for (int b = 0; b < BB; b++) {
            u64 a0 = 0, a1 = 0, c0 = 0, c1 = 0;
            const ulonglong2* hp = (const ulonglong2*)(&h_s[wid][b][0]);
            #pragma unroll
            for (int i = 0; i < 8; i++) {
                ulonglong2 v = hp[i];
                a0 = fma2(W2[2 * i + 0],      v.x, a0);
                a1 = fma2(W2[2 * i + 1],      v.y, a1);
                c0 = fma2(W2[16 + 2 * i + 0], v.x, c0);
                c1 = fma2(W2[16 + 2 * i + 1], v.y, c1);
            }
            const ulonglong2* xp = (const ulonglong2*)(&x_s[wid][b][0]);
            #pragma unroll
            for (int i = 0; i < 2; i++) {
                ulonglong2 v = xp[i];
                a0 = fma2(Wi2[2 * i + 0],     v.x, a0);
                a1 = fma2(Wi2[2 * i + 1],     v.y, a1);
                c0 = fma2(Wi2[4 + 2 * i + 0], v.x, c0);
                c1 = fma2(Wi2[4 + 2 * i + 1], v.y, c1);
            }
            float s0 = hsum2(a0) + hsum2(a1);
            float s1 = hsum2(c0) + hsum2(c1);
            if (kh == 0) { s0 += bias0; s1 += bias1; }
            *(float2*)(&zp[kh][b][row0]) = make_float2(s0, s1);
        }
        __syncthreads();                    // all zp slices complete

        // prefetch x stripe for t+1 (overlaps cell + barrier + next wait)
        if (t + 1 < TT) {
            xr = *(const float4*)(xbase + ((size_t)bx * TT + (t + 1)) * DD + dx);
        }

        // ---- cell update (1 cell/thread): sum 8 k-partials per gate ----
        {
            float zi = 0.0f, zf = 0.0f, zg = 0.0f, zo = 0.0f;
            #pragma unroll
            for (int k2 = 0; k2 < NKH; k2++) {
                zi += zp[k2][cb][cu];
                zf += zp[k2][cb][32 + cu];
                zg += zp[k2][cb][64 + cu];
                zo += zp[k2][cb][96 + cu];
            }
            float si = 1.0f / (1.0f + __expf(-zi));
            float sf = 1.0f / (1.0f + __expf(-zf));
            float so = 1.0f / (1.0f + __expf(-zo));
            creg = sf * creg + si * tanhf(zg);
            stcg(&g_H[(t + 1) & 1][g * BB + cb][r * HU + cu], so * tanhf(creg));
        }
        __syncthreads();                    // all h stores issued + zp reads done
        if (tid == 0) strel(&g_flagT[g][t][r], 1);
    }

    // ---- head: rank 0 computes sigmoid(hT @ W_out^T + b_out) ----
    if (r == 0) {
        float* hh = (float*)zp;             // reuse zp as scratch [BB][HH]
        {
            int ready = (lane < NRNK) ? 0 : 1;
            const int* fp = &g_flagT[g][TT - 1][lane & 7];
            if (!ready && ldacq(fp) != 0) ready = 1;
            while (__ballot_sync(0xFFFFFFFFu, ready) != 0xFFFFFFFFu) {
                __nanosleep(32);
                if (!ready && ldacq(fp) != 0) ready = 1;
            }
            const float* src = &g_H[0][g * BB][0] + tid * 8;   // TT&1 == 0
            float4 v0 = ldcv4(src);
            float4 v1 = ldcv4(src + 4);
            *(float4*)(hh + tid * 8)     = v0;
            *(float4*)(hh + tid * 8 + 4) = v1;
        }
        __syncthreads();
        if (tid < BB * 10) {
            int b = tid / 10, c = tid % 10;
            float acc = b_out[c];
            #pragma unroll 4
            for (int k = 0; k < HH; k++)
                acc = fmaf(hh[b * HH + k], W_out[c * HH + k], acc);
            out[(g * BB + b) * 10 + c] = 1.0f / (1.0f + __expf(-acc));
        }
    }

    // ---- end protocol: after all ranks finish polling, rank 0 resets flags ----
    __syncthreads();
    if (tid == 0) atomicAdd(&g_done[g], 1);
    if (r == 0) {
        if (tid == 0) {
            while (ldacq(&g_done[g]) < NRNK) { __nanosleep(64); }
        }
        __syncthreads();
        int* fl = &g_flagT[g][0][0];
        for (int i = tid; i < TT * NRNK; i += NTHR) fl[i] = 0;
        __syncthreads();
        if (tid == 0) { __threadfence(); g_done[g] = 0; }
    }
}

extern "C" void kernel_launch(void* const* d_in, const int* in_sizes, int n_in,
                              void* d_out, int out_size)
{
    (void)in_sizes; (void)n_in; (void)out_size;
    const float* x     = (const float*)d_in[0];
    const float* W_ih  = (const float*)d_in[1];
    const float* W_hh  = (const float*)d_in[2];
    const float* b_ih  = (const float*)d_in[3];
    const float* b_hh  = (const float*)d_in[4];
    const float* W_out = (const float*)d_in[5];
    const float* b_out = (const float*)d_in[6];
    float* outp = (float*)d_out;

    cudaFuncSetAttribute(lstm_persistent_kernel,
                         cudaFuncAttributeMaxDynamicSharedMemorySize, SMEM_BYTES);
    lstm_persistent_kernel<<<NGRP * NRNK, NTHR, SMEM_BYTES>>>(
        x, W_ih, W_hh, b_ih, b_hh, W_out, b_out, outp);
}